// round 15
// baseline (speedup 1.0000x reference)
#include <cuda_runtime.h>
#include <cuda/atomic>
#include <math.h>

#define T_DIM 1024
#define EPS 1e-7f
#define MARGIN 0.1f
#define MONO_W 0.1f
#define BETA 0.1f

#define BDIM 256            // 256 threads * float4 = 1024 cols = one row
#define ROWS 8              // rows per block
#define MAXB 32768
#define MAXBLK (MAXB / ROWS)

// Deterministic per-block partials (bce, mono, cnt, pad): each block fully
// overwrites its own slot every launch (L1-bypassed stores) -> no init pass.
__device__ float4 g_partials[MAXBLK];
// Completion counter: zero at load; last block resets to 0 -> replay-idempotent.
__device__ unsigned int g_count;

__device__ __forceinline__ float warp_red(float v) {
#pragma unroll
    for (int o = 16; o > 0; o >>= 1) v += __shfl_down_sync(0xFFFFFFFFu, v, o);
    return v;
}

__global__ __launch_bounds__(BDIM, 6) void cdf_loss_fused(
    const float* __restrict__ F,
    const long long* __restrict__ duration,
    const long long* __restrict__ event_in,
    const float* __restrict__ biases,
    float* __restrict__ out, int B)
{
    const int tid  = threadIdx.x;
    const int lane = tid & 31;
    const int wid  = tid >> 5;
    const int row0 = blockIdx.x * ROWS;
    const int c0   = tid * 4;
    const int nblk = gridDim.x;

    __shared__ float s_first[ROWS][BDIM];
    __shared__ int   s_meta[ROWS];     // d | (e << 16), uniform per row

    // per-row metadata into SMEM (register diet on the hot path)
    if (tid < ROWS) {
        const int dd = (int)duration[row0 + tid];
        const int ee = (int)event_in[row0 + tid];
        s_meta[tid] = dd | (ee << 16);
    }

    // ---- front-batched independent bulk loads (MLP = ROWS) ----
    float4 v[ROWS];
#pragma unroll
    for (int r = 0; r < ROWS; ++r) {
        const float4* rowp = reinterpret_cast<const float4*>(F + (size_t)(row0 + r) * T_DIM);
        v[r] = rowp[tid];
    }

#pragma unroll
    for (int r = 0; r < ROWS; ++r)
        s_first[r][tid] = v[r].x;
    __syncthreads();   // single barrier: meta + boundary values published

    float bce = 0.0f;
    float mono = 0.0f;

#pragma unroll
    for (int r = 0; r < ROWS; ++r) {
        const float4 w = v[r];

        // ---- monotonic term (verified mechanism) ----
        mono += fmaxf(w.x - w.y + MARGIN, 0.0f);
        mono += fmaxf(w.y - w.z + MARGIN, 0.0f);
        mono += fmaxf(w.z - w.w + MARGIN, 0.0f);
        if (tid < BDIM - 1)
            mono += fmaxf(w.w - s_first[r][tid + 1] + MARGIN, 0.0f);

        // ---- BCE term: warp-uniform case split, 1 MUFU.LG2 per group ----
        const int m  = s_meta[r];          // LDS broadcast, uniform per row
        const int dd = m & 0xFFFF;
        const int ee = m >> 16;
        const int thr = dd - ee;           // all-(1-p) iff c0+3 <= thr
        float prod;
        if (c0 + 3 <= thr) {
            prod = (1.0f - w.x) * (1.0f - w.y) * (1.0f - w.z) * (1.0f - w.w);
        } else if (ee && c0 >= dd) {
            prod = fmaxf(w.x, EPS) * fmaxf(w.y, EPS) *
                   fmaxf(w.z, EPS) * fmaxf(w.w, EPS);
        } else if (c0 <= dd) {
            const float vals[4] = {w.x, w.y, w.z, w.w};
            prod = 1.0f;
#pragma unroll
            for (int k = 0; k < 4; ++k) {
                const int c = c0 + k;
                const bool use_p = ee && (c >= dd);
                const bool msk   = ee || (c <= dd);
                const float x = use_p ? fmaxf(vals[k], EPS) : (1.0f - vals[k]);
                prod *= msk ? x : 1.0f;
            }
        } else {
            prod = 1.0f;
        }
        bce += -__logf(prod);   // __logf(1)=0 exactly
    }

    // ---- block reduction ----
    bce  = warp_red(bce);
    mono = warp_red(mono);

    __shared__ float sh_b[BDIM / 32];
    __shared__ float sh_m[BDIM / 32];
    if (lane == 0) { sh_b[wid] = bce; sh_m[wid] = mono; }
    __syncthreads();
    if (wid != 0) return;   // warps 1-7 exit now: no one waits on the atomic

    bce  = (lane < BDIM / 32) ? sh_b[lane] : 0.0f;
    mono = (lane < BDIM / 32) ? sh_m[lane] : 0.0f;
    bce = warp_red(bce);
    mono = warp_red(mono);

    unsigned int old = 0;
    if (lane == 0) {
        int cnt_blk = 0;
#pragma unroll
        for (int r = 0; r < ROWS; ++r) {
            const int m  = s_meta[r];
            cnt_blk += (m >> 16) ? T_DIM : ((m & 0xFFFF) + 1);
        }
        // publish partial to L2 (bypass L1), then release-increment the counter:
        // release orders the stcg; no membar.gpu / CCTL.IVALL.
        __stcg(&g_partials[blockIdx.x], make_float4(bce, mono, (float)cnt_blk, 0.0f));
        cuda::atomic_ref<unsigned int, cuda::thread_scope_device> cref(g_count);
        old = cref.fetch_add(1u, cuda::memory_order_acq_rel);
    }
    old = __shfl_sync(0xFFFFFFFFu, old, 0);
    if (old != (unsigned int)(nblk - 1)) return;

    // ====== last block, warp 0 only: tail reduce (partials L2-hot) ==========
    float fb0 = 0, fm0 = 0, fc0 = 0, fb1 = 0, fm1 = 0, fc1 = 0;
    float fb2 = 0, fm2 = 0, fc2 = 0, fb3 = 0, fm3 = 0, fc3 = 0;
    for (int i = lane; i < nblk; i += 128) {
        const float4 p0 = __ldcg(&g_partials[i]);
        fb0 += p0.x; fm0 += p0.y; fc0 += p0.z;
        if (i + 32 < nblk) {
            const float4 p1 = __ldcg(&g_partials[i + 32]);
            fb1 += p1.x; fm1 += p1.y; fc1 += p1.z;
        }
        if (i + 64 < nblk) {
            const float4 p2 = __ldcg(&g_partials[i + 64]);
            fb2 += p2.x; fm2 += p2.y; fc2 += p2.z;
        }
        if (i + 96 < nblk) {
            const float4 p3 = __ldcg(&g_partials[i + 96]);
            fb3 += p3.x; fm3 += p3.y; fc3 += p3.z;
        }
    }
    float fb = (fb0 + fb1) + (fb2 + fb3);
    float fm = (fm0 + fm1) + (fm2 + fm3);
    float fc = (fc0 + fc1) + (fc2 + fc3);

    float s = 0.0f;
    const float4* b4 = reinterpret_cast<const float4*>(biases);
#pragma unroll
    for (int i = lane; i < T_DIM / 4; i += 32) {
        const float4 bb = b4[i];
        s += bb.x * bb.x + bb.y * bb.y + bb.z * bb.z + bb.w * bb.w;
    }

    fb = warp_red(fb);
    fm = warp_red(fm);
    fc = warp_red(fc);
    s  = warp_red(s);

    if (lane == 0) {
        const float bceL  = fb / fc;
        const float monoL = fm / ((float)B * (float)(T_DIM - 1));
        const float bias2 = s / (float)T_DIM;
        out[0] = bceL + MONO_W * monoL + BETA * bias2;
        g_count = 0;   // reset for next replay (kernel boundary orders this)
    }
}

extern "C" void kernel_launch(void* const* d_in, const int* in_sizes, int n_in,
                              void* d_out, int out_size) {
    const float*     F      = (const float*)d_in[0];      // [B, T] fp32
    const float*     biases = (const float*)d_in[1];      // [T] fp32
    const long long* dur    = (const long long*)d_in[2];  // [B] int64
    const long long* ev     = (const long long*)d_in[3];  // [B] int64
    float* out = (float*)d_out;

    const int B = in_sizes[2];
    const int nblocks = B / ROWS;

    cdf_loss_fused<<<nblocks, BDIM>>>(F, dur, ev, biases, out, B);
}